// round 4
// baseline (speedup 1.0000x reference)
#include <cuda_runtime.h>
#include <cuda_bf16.h>

// Problem constants (fixed by setup_inputs)
#define B_CHAIN 16384
#define S_SIDE  15
#define NATM    (1 + B_CHAIN + B_CHAIN * S_SIDE)   // 262145
#define NBLK    128
#define NTHR    256
#define CHUNK   (B_CHAIN / NBLK)                   // 128 gen0 atoms / chains per block

// Cross-block scratch (no cudaMalloc allowed)
__device__ float    g_btot[NBLK * 12];   // per-block gen0 chunk totals
__device__ unsigned g_tick;              // grid-barrier ticket (monotonic across replays)

// C = A @ B for 3x4 rigid transforms, row-major [r00 r01 r02 tx | r1x | r2x]
__device__ __forceinline__ void compose(const float* __restrict__ A,
                                        const float* __restrict__ B,
                                        float* __restrict__ C) {
#pragma unroll
    for (int r = 0; r < 3; r++) {
        float a0 = A[r*4+0], a1 = A[r*4+1], a2 = A[r*4+2], a3 = A[r*4+3];
        C[r*4+0] = a0*B[0] + a1*B[4] + a2*B[8];
        C[r*4+1] = a0*B[1] + a1*B[5] + a2*B[9];
        C[r*4+2] = a0*B[2] + a1*B[6] + a2*B[10];
        C[r*4+3] = a0*B[3] + a1*B[7] + a2*B[11] + a3;
    }
}

__device__ __forceinline__ void mat_copy(float* __restrict__ d, const float* __restrict__ s) {
#pragma unroll
    for (int k = 0; k < 12; k++) d[k] = s[k];
}

__device__ __forceinline__ void mat_ident(float* __restrict__ d) {
    d[0]=1.f; d[1]=0.f; d[2]=0.f; d[3]=0.f;
    d[4]=0.f; d[5]=1.f; d[6]=0.f; d[7]=0.f;
    d[8]=0.f; d[9]=0.f; d[10]=1.f; d[11]=0.f;
}

// Bond transform: Rx(d0) Rz(d1) T(d2,0,0) Rx(d3), closed form.
// FAST uses __sincosf (side chains only; depth <= 15, no deep error accumulation).
template <bool FAST>
__device__ __forceinline__ void bond_ht(float d0, float d1, float d2, float d3,
                                        float* __restrict__ M) {
    float sa, ca, sb, cb, sd, cd;
    if (FAST) {
        __sincosf(d0, &sa, &ca);
        __sincosf(d1, &sb, &cb);
        __sincosf(d3, &sd, &cd);
    } else {
        sincosf(d0, &sa, &ca);
        sincosf(d1, &sb, &cb);
        sincosf(d3, &sd, &cd);
    }
    M[0] = cb;     M[1] = -sb*cd;            M[2]  = sb*sd;             M[3]  = d2*cb;
    M[4] = ca*sb;  M[5] = ca*cb*cd - sa*sd;  M[6]  = -ca*cb*sd - sa*cd; M[7]  = ca*d2*sb;
    M[8] = sa*sb;  M[9] = sa*cb*cd + ca*sd;  M[10] = -sa*cb*sd + ca*cd; M[11] = sa*d2*sb;
}

// Atom 1 jump (d4=d5=0): T(d0,d1,d2) @ Rx(d3)
__device__ __forceinline__ void jump_ht(float d0, float d1, float d2, float d3,
                                        float* __restrict__ M) {
    float sd, cd; sincosf(d3, &sd, &cd);
    M[0] = 1.f; M[1] = 0.f; M[2] = 0.f;  M[3]  = d0;
    M[4] = 0.f; M[5] = cd;  M[6] = -sd;  M[7]  = d1;
    M[8] = 0.f; M[9] = sd;  M[10] = cd;  M[11] = d2;
}

__device__ __forceinline__ void shfl_mat(float* __restrict__ P,
                                         const float* __restrict__ M,
                                         int off, int width) {
#pragma unroll
    for (int k = 0; k < 12; k++)
        P[k] = __shfl_up_sync(0xffffffffu, M[k], off, width);
}

__global__ void __launch_bounds__(NTHR) k_fused(const float* __restrict__ dofs,
                                                const int* __restrict__ kin_id,
                                                float* __restrict__ out) {
    __shared__ float s_scan[CHUNK * 12];   // 6 KB: this block's gen0 inclusive scans
    __shared__ float s_w[4 * 12];          // warp totals (reused phase1 / phase2)
    __shared__ float s_pref[12];           // this block's exclusive prefix

    const int b    = blockIdx.x;
    const int tid  = threadIdx.x;
    const int lane = tid & 31;
    const int wid  = tid >> 5;

    // ---- Prefetch phase-3 data into L1 (L1 persists within launch) ----
    {
        const char* p0 = (const char*)(dofs + 4 * (B_CHAIN + b * CHUNK * S_SIDE));
        const int bytes0 = CHUNK * S_SIDE * 16;            // 30720 B of side dofs
        for (int off = tid * 128; off < bytes0; off += NTHR * 128)
            asm volatile("prefetch.global.L1 [%0];" :: "l"(p0 + off));
        const char* p1 = (const char*)(kin_id + 1 + B_CHAIN + b * CHUNK * S_SIDE);
        const int bytes1 = CHUNK * S_SIDE * 4;             // 7680 B of side kin_id
        for (int off = tid * 128; off < bytes1; off += NTHR * 128)
            asm volatile("prefetch.global.L1 [%0];" :: "l"(p1 + off));
    }

    // ---- Phase 1: scan this block's gen0 chunk (threads 0..CHUNK-1) ----
    float M1[12];
    if (tid < CHUNK) {
        const int gi = b * CHUNK + tid;          // atom gi+1
        const float4 d = __ldg((const float4*)(dofs + 4 * gi));
        if (gi == 0) jump_ht(d.x, d.y, d.z, d.w, M1);
        else         bond_ht<false>(d.x, d.y, d.z, d.w, M1);

#pragma unroll
        for (int off = 1; off < 32; off <<= 1) {
            float P[12], C[12];
            shfl_mat(P, M1, off, 32);
            compose(P, M1, C);
            if (lane >= off) mat_copy(M1, C);
        }
        if (lane == 31) mat_copy(&s_w[wid * 12], M1);
    }
    __syncthreads();

    if (tid < CHUNK) {
        float W[12]; mat_ident(W);
        for (int i = 0; i < wid; i++) {      // wid < 4 here
            float C[12];
            compose(W, &s_w[i * 12], C);
            mat_copy(W, C);
        }
        float F[12];
        compose(W, M1, F);
        mat_copy(&s_scan[tid * 12], F);
        if (tid == CHUNK - 1) mat_copy(&g_btot[b * 12], F);
    }
    __syncthreads();   // all writes (incl. g_btot) ordered before leader's fence

    // ---- Grid barrier (ticketed; exactly NBLK tickets per launch -> replay-safe) ----
    if (tid == 0) {
        __threadfence();
        unsigned t = atomicAdd(&g_tick, 1u);
        unsigned target = (t / NBLK + 1u) * NBLK;
        unsigned v;
        do {
            asm volatile("ld.acquire.gpu.u32 %0, [%1];"
                         : "=r"(v) : "l"(&g_tick) : "memory");
        } while (v < target);
    }
    __syncthreads();

    // ---- Phase 2: every block redundantly computes its exclusive prefix ----
    if (tid < NBLK) {
        float M2[12];
        mat_copy(M2, &g_btot[tid * 12]);
#pragma unroll
        for (int off = 1; off < 32; off <<= 1) {
            float P[12], C[12];
            shfl_mat(P, M2, off, 32);
            compose(P, M2, C);
            if (lane >= off) mat_copy(M2, C);
        }
        if (lane == 31) mat_copy(&s_w[wid * 12], M2);
        __syncthreads();

        float W[12]; mat_ident(W);
        for (int i = 0; i < wid; i++) {
            float C[12];
            compose(W, &s_w[i * 12], C);
            mat_copy(W, C);
        }
        float F[12];
        compose(W, M2, F);                 // inclusive over btot[0..tid]

        if (b == 0) {
            if (tid == 0) { float I[12]; mat_ident(I); mat_copy(s_pref, I); }
        } else if (tid == b - 1) {
            mat_copy(s_pref, F);           // exclusive prefix for block b
        }
    } else {
        __syncthreads();                   // match the barrier above
    }
    __syncthreads();

    float P[12];
    mat_copy(P, s_pref);

    // ---- Phase 3: apply. 16 lanes per chain, 16 chains per iteration ----
#pragma unroll 2
    for (int it = 0; it < (CHUNK * 16) / NTHR; ++it) {    // 8 iterations
        const int l = it * (NTHR / 16) + (tid >> 4);      // local chain 0..127
        const int j = tid & 15;                           // 0 = parent, 1..15 side
        const int c = b * CHUNK + l;

        int atom;
        float M[12];
        if (j == 0) {
            atom = c + 1;
            compose(P, &s_scan[l * 12], M);
        } else {
            atom = 1 + B_CHAIN + c * S_SIDE + (j - 1);
            const float4 d = __ldg((const float4*)(dofs + 4 * (atom - 1)));
            bond_ht<true>(d.x, d.y, d.z, d.w, M);
        }
        const int kid = __ldg(&kin_id[atom]);

#pragma unroll
        for (int off = 1; off < 16; off <<= 1) {
            float Q[12], C[12];
            shfl_mat(Q, M, off, 16);
            compose(Q, M, C);
            if (j >= off) mat_copy(M, C);
        }

        out[3 * kid + 0] = M[3];
        out[3 * kid + 1] = M[7];
        out[3 * kid + 2] = M[11];
    }
}

extern "C" void kernel_launch(void* const* d_in, const int* in_sizes, int n_in,
                              void* d_out, int out_size) {
    const float* dofs   = (const float*)d_in[0];   // (NATM-1)*4
    const int*   kin_id = (const int*)  d_in[8];   // NATM
    float*       out    = (float*)d_out;           // (NATM-1)*3

    k_fused<<<NBLK, NTHR>>>(dofs, kin_id, out);
}

// round 8
// speedup vs baseline: 1.1210x; 1.1210x over previous
#include <cuda_runtime.h>
#include <cuda_bf16.h>

// Problem constants (fixed by setup_inputs)
#define B_CHAIN 16384
#define S_SIDE  15
#define NATM    (1 + B_CHAIN + B_CHAIN * S_SIDE)   // 262145
#define NBLK    128
#define CHUNK   (B_CHAIN / NBLK)                   // 128 gen0 atoms per block
#define K2_THR  1024

// Cross-kernel scratch (no cudaMalloc allowed)
__device__ float g_btot[NBLK * 12];      // per-block gen0 chunk totals

// C = A @ B for 3x4 rigid transforms, row-major [r00 r01 r02 tx | r1x | r2x]
__device__ __forceinline__ void compose(const float* __restrict__ A,
                                        const float* __restrict__ B,
                                        float* __restrict__ C) {
#pragma unroll
    for (int r = 0; r < 3; r++) {
        float a0 = A[r*4+0], a1 = A[r*4+1], a2 = A[r*4+2], a3 = A[r*4+3];
        C[r*4+0] = a0*B[0] + a1*B[4] + a2*B[8];
        C[r*4+1] = a0*B[1] + a1*B[5] + a2*B[9];
        C[r*4+2] = a0*B[2] + a1*B[6] + a2*B[10];
        C[r*4+3] = a0*B[3] + a1*B[7] + a2*B[11] + a3;
    }
}

__device__ __forceinline__ void mat_copy(float* __restrict__ d, const float* __restrict__ s) {
#pragma unroll
    for (int k = 0; k < 12; k++) d[k] = s[k];
}

__device__ __forceinline__ void mat_ident(float* __restrict__ d) {
    d[0]=1.f; d[1]=0.f; d[2]=0.f; d[3]=0.f;
    d[4]=0.f; d[5]=1.f; d[6]=0.f; d[7]=0.f;
    d[8]=0.f; d[9]=0.f; d[10]=1.f; d[11]=0.f;
}

// Bond transform: Rx(d0) Rz(d1) T(d2,0,0) Rx(d3), closed form, fast trig.
__device__ __forceinline__ void bond_ht(float d0, float d1, float d2, float d3,
                                        float* __restrict__ M) {
    float sa, ca, sb, cb, sd, cd;
    __sincosf(d0, &sa, &ca);
    __sincosf(d1, &sb, &cb);
    __sincosf(d3, &sd, &cd);
    M[0] = cb;     M[1] = -sb*cd;            M[2]  = sb*sd;             M[3]  = d2*cb;
    M[4] = ca*sb;  M[5] = ca*cb*cd - sa*sd;  M[6]  = -ca*cb*sd - sa*cd; M[7]  = ca*d2*sb;
    M[8] = sa*sb;  M[9] = sa*cb*cd + ca*sd;  M[10] = -sa*cb*sd + ca*cd; M[11] = sa*d2*sb;
}

// Atom 1 jump (d4=d5=0): T(d0,d1,d2) @ Rx(d3)
__device__ __forceinline__ void jump_ht(float d0, float d1, float d2, float d3,
                                        float* __restrict__ M) {
    float sd, cd; __sincosf(d3, &sd, &cd);
    M[0] = 1.f; M[1] = 0.f; M[2] = 0.f;  M[3]  = d0;
    M[4] = 0.f; M[5] = cd;  M[6] = -sd;  M[7]  = d1;
    M[8] = 0.f; M[9] = sd;  M[10] = cd;  M[11] = d2;
}

__device__ __forceinline__ void shfl_up_mat(float* __restrict__ P,
                                            const float* __restrict__ M,
                                            int off, int width) {
#pragma unroll
    for (int k = 0; k < 12; k++)
        P[k] = __shfl_up_sync(0xffffffffu, M[k], off, width);
}

__device__ __forceinline__ void shfl_dn_mat(float* __restrict__ P,
                                            const float* __restrict__ M,
                                            int off) {
#pragma unroll
    for (int k = 0; k < 12; k++)
        P[k] = __shfl_down_sync(0xffffffffu, M[k], off);
}

// Local ht for gen0 index gi (atom gi+1)
__device__ __forceinline__ void gen0_ht(const float* __restrict__ dofs,
                                        int gi, float* __restrict__ M) {
    const float4 d = __ldg((const float4*)(dofs + 4 * gi));
    if (gi == 0) jump_ht(d.x, d.y, d.z, d.w, M);
    else         bond_ht(d.x, d.y, d.z, d.w, M);
}

// Warp inclusive scan (order-preserving, width 32)
__device__ __forceinline__ void warp_scan(float* __restrict__ M, int lane) {
#pragma unroll
    for (int off = 1; off < 32; off <<= 1) {
        float P[12], C[12];
        shfl_up_mat(P, M, off, 32);
        compose(P, M, C);
        if (lane >= off) mat_copy(M, C);
    }
}

// ---------------- K1: per-block chunk totals only ----------------
__global__ void __launch_bounds__(CHUNK) k_totals(const float* __restrict__ dofs) {
    __shared__ float s_w[4 * 12];
    const int tid  = threadIdx.x;
    const int lane = tid & 31;
    const int wid  = tid >> 5;
    const int gi   = blockIdx.x * CHUNK + tid;

    float M[12];
    gen0_ht(dofs, gi, M);

    // warp product reduction (order-preserving): lane0 ends with v0∘...∘v31
#pragma unroll
    for (int off = 1; off < 32; off <<= 1) {
        float P[12], C[12];
        shfl_dn_mat(P, M, off);
        compose(M, P, C);
        mat_copy(M, C);           // lanes past the end hold garbage; lane0 correct
    }
    if (lane == 0) mat_copy(&s_w[wid * 12], M);
    __syncthreads();

    if (tid == 0) {
        float T[12], C[12];
        mat_copy(T, &s_w[0]);
#pragma unroll
        for (int i = 1; i < 4; i++) { compose(T, &s_w[i * 12], C); mat_copy(T, C); }
        mat_copy(&g_btot[blockIdx.x * 12], T);
    }
}

// ---------------- K2: scan-redo + prefix + apply, fused ----------------
__global__ void __launch_bounds__(K2_THR)
k_apply(const float* __restrict__ dofs,
        const int* __restrict__ kin_id,
        float* __restrict__ out) {
    __shared__ float s_scan[CHUNK * 12];    // 6 KB: chunk inclusive scans
    __shared__ float s_wA[4 * 12];          // warp totals, group A
    __shared__ float s_wB[4 * 12];          // warp totals, group B
    __shared__ float s_pref[12];            // exclusive prefix for this block

    const int b    = blockIdx.x;
    const int tid  = threadIdx.x;
    const int lane = tid & 31;

    float MA[12], MB[12];

    if (tid < CHUNK) {
        // ---- Group A (warps 0-3): recompute chunk inclusive scan ----
        gen0_ht(dofs, b * CHUNK + tid, MA);
        warp_scan(MA, lane);
        if (lane == 31) mat_copy(&s_wA[(tid >> 5) * 12], MA);
    } else if (tid < 2 * CHUNK) {
        // ---- Group B (warps 4-7): scan the 128 block totals ----
        const int t2 = tid - CHUNK;
        mat_copy(MB, &g_btot[t2 * 12]);
        warp_scan(MB, lane);
        if (lane == 31) mat_copy(&s_wB[(t2 >> 5) * 12], MB);
    }
    __syncthreads();

    if (tid < CHUNK) {
        // group A cross-warp combine -> s_scan
        const int wid = tid >> 5;
        float W[12]; mat_ident(W);
        for (int i = 0; i < wid; i++) {
            float C[12]; compose(W, &s_wA[i * 12], C); mat_copy(W, C);
        }
        float F[12]; compose(W, MA, F);
        mat_copy(&s_scan[tid * 12], F);
    } else if (tid < 2 * CHUNK) {
        // group B cross-warp combine -> exclusive prefix for block b
        const int t2  = tid - CHUNK;
        const int wid = t2 >> 5;
        float W[12]; mat_ident(W);
        for (int i = 0; i < wid; i++) {
            float C[12]; compose(W, &s_wB[i * 12], C); mat_copy(W, C);
        }
        float F[12]; compose(W, MB, F);      // inclusive over btot[0..t2]
        if (b == 0) {
            if (t2 == 0) { float I[12]; mat_ident(I); mat_copy(s_pref, I); }
        } else if (t2 == b - 1) {
            mat_copy(s_pref, F);
        }
    }
    __syncthreads();

    float P[12];
    mat_copy(P, s_pref);

    // ---- Phase 3: 16 lanes per chain, 64 chains per iteration, 2 iterations ----
#pragma unroll
    for (int it = 0; it < (CHUNK * 16) / K2_THR; ++it) {
        const int l = it * (K2_THR / 16) + (tid >> 4);   // local chain 0..127
        const int j = tid & 15;                          // 0 = parent, 1..15 side
        const int c = b * CHUNK + l;

        int atom;
        float M[12];
        if (j == 0) {
            atom = c + 1;
            compose(P, &s_scan[l * 12], M);
        } else {
            atom = 1 + B_CHAIN + c * S_SIDE + (j - 1);
            const float4 d = __ldg((const float4*)(dofs + 4 * (atom - 1)));
            bond_ht(d.x, d.y, d.z, d.w, M);
        }
        const int kid = __ldg(&kin_id[atom]);

#pragma unroll
        for (int off = 1; off < 16; off <<= 1) {
            float Q[12], C[12];
            shfl_up_mat(Q, M, off, 16);
            compose(Q, M, C);
            if (j >= off) mat_copy(M, C);
        }

        out[3 * kid + 0] = M[3];
        out[3 * kid + 1] = M[7];
        out[3 * kid + 2] = M[11];
    }
}

extern "C" void kernel_launch(void* const* d_in, const int* in_sizes, int n_in,
                              void* d_out, int out_size) {
    const float* dofs   = (const float*)d_in[0];   // (NATM-1)*4
    const int*   kin_id = (const int*)  d_in[8];   // NATM
    float*       out    = (float*)d_out;           // (NATM-1)*3

    k_totals<<<NBLK, CHUNK>>>(dofs);
    k_apply<<<NBLK, K2_THR>>>(dofs, kin_id, out);
}